// round 15
// baseline (speedup 1.0000x reference)
#include <cuda_runtime.h>
#include <math.h>
#include <stdint.h>

#define BATCH 8192
#define PDIM  512
#define DM    256
#define DI    512
#define DTR   16
#define DS    16
#define ADIM  64
#define XDW   48

// ---- static scratch ----
__device__ float g_P[BATCH * PDIM];
__device__ float g_W[417792];            // tf32 weights: W_in | in_proj | x_proj
__device__ float g_WC[128 * DI];
__device__ float g_X[BATCH * DM];
__device__ float g_U2[BATCH * DI];
__device__ float g_G[BATCH * DI];
__device__ float g_XD[4 * BATCH * XDW];
__device__ float g_Y[BATCH * DI];
__device__ float g_HP[2 * BATCH * 128];

#define OFF_WIN   0
#define OFF_INPJ  131072
#define OFF_XPJ   393216
#define NW_TOTAL  417792
#define NP_TOTAL  (BATCH * PDIM)

__device__ __forceinline__ float cvt_tf32(float x) {
    uint32_t u;
    asm("cvt.rna.tf32.f32 %0, %1;" : "=r"(u) : "f"(x));
    return __uint_as_float(u);
}

__device__ __forceinline__ void mma_tf32(float* c, const uint32_t* a,
                                         uint32_t b0, uint32_t b1) {
    asm volatile(
        "mma.sync.aligned.m16n8k8.row.col.f32.tf32.tf32.f32 "
        "{%0,%1,%2,%3},{%4,%5,%6,%7},{%8,%9},{%0,%1,%2,%3};"
        : "+f"(c[0]), "+f"(c[1]), "+f"(c[2]), "+f"(c[3])
        : "r"(a[0]), "r"(a[1]), "r"(a[2]), "r"(a[3]), "r"(b0), "r"(b1));
}

__device__ __forceinline__ void cp16(uint32_t dst, const float* src, bool ok) {
    int sz = ok ? 16 : 0;
    asm volatile("cp.async.ca.shared.global [%0], [%1], 16, %2;"
                 :: "r"(dst), "l"(src), "r"(sz) : "memory");
}
#define CP_COMMIT() asm volatile("cp.async.commit_group;" ::: "memory")
#define CP_WAIT1()  asm volatile("cp.async.wait_group 1;" ::: "memory")

__device__ __forceinline__ float fast_sigmoid(float x) {
    return __fdividef(1.f, 1.f + __expf(-x));
}
__device__ __forceinline__ float fast_softplus(float x) {
    return (x > 15.f) ? x : __logf(1.f + __expf(x));
}
__device__ __forceinline__ float fast_tanh(float x) {
    float e = __expf(-2.f * fabsf(x));
    float t = __fdividef(1.f - e, 1.f + e);
    return copysignf(t, x);
}

__global__ void __launch_bounds__(256)
preround(const float* __restrict__ P,
         const float* __restrict__ w_in,  const float* __restrict__ in_proj,
         const float* __restrict__ x_proj,
         float* __restrict__ gP, float* __restrict__ gW) {
    int idx = blockIdx.x * 256 + threadIdx.x;
    if (idx < NP_TOTAL) { gP[idx] = cvt_tf32(P[idx]); return; }
    int j = idx - NP_TOTAL;
    if (j >= NW_TOTAL) return;
    float v;
    if      (j < OFF_INPJ) v = w_in[j - OFF_WIN];
    else if (j < OFF_XPJ)  v = in_proj[j - OFF_INPJ];
    else                   v = x_proj[j - OFF_XPJ];
    gW[j] = cvt_tf32(v);
}

__global__ void __launch_bounds__(256)
combine_heads(const float* __restrict__ mu_w, const float* __restrict__ ls_w,
              const float* __restrict__ out_proj, float* __restrict__ WC) {
    __shared__ float sM[64][65];
    __shared__ float sO[64][65];
    const int tid = threadIdx.x;
    const int bj = blockIdx.x * 64, bd = blockIdx.y * 64;
    const int ty = tid >> 4, tx = tid & 15;

    float acc[4][4];
#pragma unroll
    for (int i = 0; i < 4; i++)
#pragma unroll
        for (int j = 0; j < 4; j++) acc[i][j] = 0.f;

    for (int k0 = 0; k0 < DM; k0 += 64) {
        for (int i = tid; i < 64 * 16; i += 256) {
            int r = i >> 4, q = (i & 15) * 4;
            int jr = bj + r;
            const float* src = (jr < ADIM)
                ? (mu_w + (size_t)jr * DM + k0 + q)
                : (ls_w + (size_t)(jr - ADIM) * DM + k0 + q);
            float4 v = *(const float4*)src;
            sM[r][q] = v.x; sM[r][q + 1] = v.y; sM[r][q + 2] = v.z; sM[r][q + 3] = v.w;
        }
        for (int i = tid; i < 64 * 16; i += 256) {
            int r = i >> 4, q = (i & 15) * 4;
            float4 v = *(const float4*)(out_proj + (size_t)(k0 + r) * DI + bd + q);
            sO[r][q] = v.x; sO[r][q + 1] = v.y; sO[r][q + 2] = v.z; sO[r][q + 3] = v.w;
        }
        __syncthreads();
#pragma unroll 8
        for (int k = 0; k < 64; k++) {
            float a[4], b[4];
#pragma unroll
            for (int i = 0; i < 4; i++) { a[i] = sM[ty * 4 + i][k]; b[i] = sO[k][tx * 4 + i]; }
#pragma unroll
            for (int i = 0; i < 4; i++)
#pragma unroll
                for (int j = 0; j < 4; j++) acc[i][j] += a[i] * b[j];
        }
        __syncthreads();
    }
#pragma unroll
    for (int i = 0; i < 4; i++)
#pragma unroll
        for (int j = 0; j < 4; j++)
            WC[(size_t)(bj + ty * 4 + i) * DI + bd + tx * 4 + j] = cvt_tf32(acc[i][j]);
}

// ---------- 64x64 GEMM, 128 threads (4 warps, 32x32 each), BK=16 ----------
// High-occupancy variant: ~7 CTAs/SM resident (44% occ).
// EPI: 0 split-K partial (guard col<Nfull), 1 X=cvt(v+bias), 2 in_proj fused
template <int EPI>
__global__ void __launch_bounds__(128)
gemm64(const float* __restrict__ A, int lda,
       const float* __restrict__ W, int ldw, const float* __restrict__ bias,
       float* __restrict__ C, int ldc, int Nfull, int K, int pstride,
       const float* __restrict__ aux0, const float* __restrict__ aux1,
       float* __restrict__ aux2) {
    const int BM = 64, BN = 64, BK = 16, PAD = 20;
    __shared__ float As[3][BM][PAD];
    __shared__ float Ws[3][BN][PAD];

    const int tid  = threadIdx.x;
    const int lane = tid & 31, wid = tid >> 5;   // 4 warps
    const int wm = (wid & 1) * 32, wn = (wid >> 1) * 32;
    const int g = lane >> 2, t = lane & 3;
    const int bm = blockIdx.x * BM;
    const int bn = blockIdx.y * BN;

    const int kz = blockIdx.z * K;
    const float* Ap = A + kz;
    const float* Wp = W + kz;
    float* Cz = (EPI == 0) ? (C + (size_t)blockIdx.z * pstride) : C;

    const int ar0 = tid >> 2;            // 0..31
    const int ak  = (tid & 3) * 4;
    const int nTiles = K / BK;

    const bool wok0 = (bn + ar0) < Nfull;
    const bool wok1 = (bn + ar0 + 32) < Nfull;
    const int wr0 = wok0 ? (bn + ar0) : 0;
    const int wr1 = wok1 ? (bn + ar0 + 32) : 0;

    uint32_t sA0 = (uint32_t)__cvta_generic_to_shared(&As[0][ar0][ak]);
    uint32_t sA1 = (uint32_t)__cvta_generic_to_shared(&As[0][ar0 + 32][ak]);
    uint32_t sW0 = (uint32_t)__cvta_generic_to_shared(&Ws[0][ar0][ak]);
    uint32_t sW1 = (uint32_t)__cvta_generic_to_shared(&Ws[0][ar0 + 32][ak]);
    const uint32_t bufA = BM * PAD * 4;
    const uint32_t bufW = BN * PAD * 4;

    auto issue = [&](int kt, int b) {
        int k0 = kt * BK + ak;
        cp16(sA0 + b * bufA, Ap + (size_t)(bm + ar0) * lda + k0, true);
        cp16(sA1 + b * bufA, Ap + (size_t)(bm + ar0 + 32) * lda + k0, true);
        cp16(sW0 + b * bufW, Wp + (size_t)wr0 * ldw + k0, wok0);
        cp16(sW1 + b * bufW, Wp + (size_t)wr1 * ldw + k0, wok1);
    };

    float acc[2][4][4];
#pragma unroll
    for (int i = 0; i < 2; i++)
#pragma unroll
        for (int j = 0; j < 4; j++)
#pragma unroll
            for (int l = 0; l < 4; l++) acc[i][j][l] = 0.f;

    issue(0, 0); CP_COMMIT();
    issue(1, 1); CP_COMMIT();

    int cur = 0;
    for (int kt = 0; kt < nTiles; kt++) {
        CP_WAIT1();
        __syncthreads();
        if (kt + 2 < nTiles) issue(kt + 2, (kt + 2) % 3);
        CP_COMMIT();

#pragma unroll
        for (int ks = 0; ks < 2; ks++) {
            const int kb = ks * 8;
            uint32_t a[2][4];
#pragma unroll
            for (int mt = 0; mt < 2; mt++) {
                int row = wm + mt * 16 + g;
                a[mt][0] = __float_as_uint(As[cur][row][kb + t]);
                a[mt][1] = __float_as_uint(As[cur][row + 8][kb + t]);
                a[mt][2] = __float_as_uint(As[cur][row][kb + t + 4]);
                a[mt][3] = __float_as_uint(As[cur][row + 8][kb + t + 4]);
            }
#pragma unroll
            for (int nt = 0; nt < 4; nt++) {
                int nc = wn + nt * 8 + g;
                uint32_t b0 = __float_as_uint(Ws[cur][nc][kb + t]);
                uint32_t b1 = __float_as_uint(Ws[cur][nc][kb + t + 4]);
                mma_tf32(acc[0][nt], a[0], b0, b1);
                mma_tf32(acc[1][nt], a[1], b0, b1);
            }
        }
        cur = (cur + 1) % 3;
    }

#pragma unroll
    for (int mt = 0; mt < 2; mt++) {
#pragma unroll
        for (int nt = 0; nt < 4; nt++) {
#pragma unroll
            for (int ci = 0; ci < 4; ci++) {
                int row = bm + wm + mt * 16 + g + ((ci >= 2) ? 8 : 0);
                int col = bn + wn + nt * 8 + t * 2 + (ci & 1);
                float v = acc[mt][nt][ci];
                if (EPI == 0) {
                    if (col < Nfull) Cz[(size_t)row * ldc + col] = v;
                } else if (EPI == 1) {
                    C[(size_t)row * ldc + col] = cvt_tf32(v + bias[col]);
                } else { // EPI == 2: in_proj fused
                    if (col < DI) {
                        float u = v * aux0[col * 4 + 3] + aux1[col];
                        C[(size_t)row * DI + col] = cvt_tf32(u * fast_sigmoid(u)); // U2
                    } else {
                        aux2[(size_t)row * DI + (col - DI)] = v * fast_sigmoid(v); // G
                    }
                }
            }
        }
    }
}

__global__ void __launch_bounds__(256)
heads_epi(const float* __restrict__ HP, const float* __restrict__ mu_b,
          const float* __restrict__ ls_b, float* __restrict__ out_mu,
          float* __restrict__ out_ls) {
    int idx = (blockIdx.x * 256 + threadIdx.x) * 4;
    int row = idx >> 7, col = idx & 127;
    float4 p0 = *(const float4*)&HP[idx];
    float4 p1 = *(const float4*)&HP[(size_t)BATCH * 128 + idx];
    if (col < ADIM) {
        const float4 b = *(const float4*)&mu_b[col];
        float4 o;
        o.x = fast_tanh(p0.x + p1.x + b.x);
        o.y = fast_tanh(p0.y + p1.y + b.y);
        o.z = fast_tanh(p0.z + p1.z + b.z);
        o.w = fast_tanh(p0.w + p1.w + b.w);
        *(float4*)&out_mu[(size_t)row * ADIM + col] = o;
    } else {
        const float4 b = *(const float4*)&ls_b[col - ADIM];
        float4 o;
        o.x = fminf(fmaxf(p0.x + p1.x + b.x, -5.f), 2.f);
        o.y = fminf(fmaxf(p0.y + p1.y + b.y, -5.f), 2.f);
        o.z = fminf(fmaxf(p0.z + p1.z + b.z, -5.f), 2.f);
        o.w = fminf(fmaxf(p0.w + p1.w + b.w, -5.f), 2.f);
        *(float4*)&out_ls[(size_t)row * ADIM + (col - ADIM)] = o;
    }
}

#define RB2 8
__global__ void __launch_bounds__(512)
delta_ygate(const float* __restrict__ XD, const float* __restrict__ dtw,
            const float* __restrict__ dtb, const float* __restrict__ U2,
            const float* __restrict__ G, const float* __restrict__ Dskip,
            float* __restrict__ Y) {
    __shared__ float sXD[RB2][XDW];
    __shared__ float sbc[RB2];
    const int tid = threadIdx.x;
    const int r0 = blockIdx.x * RB2;

    if (tid < RB2 * 12) {
        int r = tid / 12, c4 = (tid % 12) * 4;
        size_t off = (size_t)(r0 + r) * XDW + c4;
        float4 s = *(const float4*)&XD[off];
#pragma unroll
        for (int p = 1; p < 4; p++) {
            float4 xp = *(const float4*)&XD[(size_t)p * BATCH * XDW + off];
            s.x += xp.x; s.y += xp.y; s.z += xp.z; s.w += xp.w;
        }
        *(float4*)&sXD[r][c4] = s;
    }
    __syncthreads();
    if (tid < RB2) {
        float s = 0.f;
#pragma unroll
        for (int k = 0; k < DS; k++) s += sXD[tid][DTR + k] * sXD[tid][DTR + DS + k];
        sbc[tid] = s;
    }

    float w[DTR];
#pragma unroll
    for (int i = 0; i < 4; i++)
        *(float4*)&w[i * 4] = *(const float4*)(dtw + (size_t)tid * DTR + i * 4);
    const float bv = dtb[tid];
    const float dv = Dskip[tid];
    __syncthreads();

    size_t base = (size_t)r0 * DI;
    float u = U2[base + tid];
    float gg = G[base + tid];
#pragma unroll
    for (int r = 0; r < RB2; r++) {
        float un, gn;
        if (r + 1 < RB2) {
            un = U2[base + DI + tid];
            gn = G[base + DI + tid];
        }
        float acc = bv;
#pragma unroll
        for (int k = 0; k < DTR; k++) acc += w[k] * sXD[r][k];
        float de = fast_softplus(acc);
        Y[base + tid] = cvt_tf32(u * (de * sbc[r] + dv) * gg);
        base += DI;
        u = un; gg = gn;
    }
}

extern "C" void kernel_launch(void* const* d_in, const int* in_sizes, int n_in,
                              void* d_out, int out_size) {
    const float* perception = (const float*)d_in[0];
    const float* W_in       = (const float*)d_in[1];
    const float* b_in       = (const float*)d_in[2];
    const float* mu_w       = (const float*)d_in[3];
    const float* mu_b       = (const float*)d_in[4];
    const float* ls_w       = (const float*)d_in[5];
    const float* ls_b       = (const float*)d_in[6];
    const float* in_proj_w  = (const float*)d_in[7];
    const float* conv_w     = (const float*)d_in[8];
    const float* conv_b     = (const float*)d_in[9];
    const float* x_proj_w   = (const float*)d_in[10];
    const float* dt_proj_w  = (const float*)d_in[11];
    const float* dt_proj_b  = (const float*)d_in[12];
    const float* Dskip      = (const float*)d_in[14];
    const float* out_proj_w = (const float*)d_in[15];

    float* out = (float*)d_out;

    float *P, *Wts, *WC, *X, *U2, *G, *XD, *Y, *HP;
    cudaGetSymbolAddress((void**)&P,   g_P);
    cudaGetSymbolAddress((void**)&Wts, g_W);
    cudaGetSymbolAddress((void**)&WC,  g_WC);
    cudaGetSymbolAddress((void**)&X,   g_X);
    cudaGetSymbolAddress((void**)&U2,  g_U2);
    cudaGetSymbolAddress((void**)&G,   g_G);
    cudaGetSymbolAddress((void**)&XD,  g_XD);
    cudaGetSymbolAddress((void**)&Y,   g_Y);
    cudaGetSymbolAddress((void**)&HP,  g_HP);

    const int MB = BATCH / 64;    // 128 M-tiles

    // 0) pre-round + fold heads through out_proj
    preround<<<(NP_TOTAL + NW_TOTAL + 255) / 256, 256>>>(
        perception, W_in, in_proj_w, x_proj_w, P, Wts);
    combine_heads<<<dim3(2, 8), 256>>>(mu_w, ls_w, out_proj_w, WC);

    // 1) X = cvt(perc @ W_in^T + b_in)       [8192,256] K=512  (grid 512)
    gemm64<1><<<dim3(MB, DM / 64), 128>>>(P, PDIM, Wts + OFF_WIN, PDIM, b_in,
                                          X, DM, DM, PDIM, 0,
                                          nullptr, nullptr, nullptr);
    // 2) in_proj + silu-conv + silu(z)       [8192,1024] K=256 (grid 2048)
    gemm64<2><<<dim3(MB, (2 * DI) / 64), 128>>>(X, DM, Wts + OFF_INPJ, DM,
                                                nullptr, U2, DI, 2 * DI, DM, 0,
                                                conv_w, conv_b, G);
    // 3) XD partials = U2 @ x_proj^T (split-K x4) [8192,48] (grid 512)
    gemm64<0><<<dim3(MB, 1, 4), 128>>>(U2, DI, Wts + OFF_XPJ, DI, nullptr,
                                       XD, XDW, XDW, 128, BATCH * XDW,
                                       nullptr, nullptr, nullptr);
    // 4) delta + bc + gate -> Y              [8192,512]
    delta_ygate<<<BATCH / RB2, 512>>>(XD, dt_proj_w, dt_proj_b, U2, G, Dskip, Y);
    // 5) head partials = Y @ WC^T (split-K x2) [8192,128] (grid 512)
    gemm64<0><<<dim3(MB, 2, 2), 128>>>(Y, DI, WC, DI, nullptr,
                                       HP, 128, 128, 256, BATCH * 128,
                                       nullptr, nullptr, nullptr);
    // 6) heads epilogue
    heads_epi<<<(BATCH * 128) / (256 * 4), 256>>>(HP, mu_b, ls_b,
                                                  out, out + (size_t)BATCH * ADIM);
    (void)in_sizes; (void)n_in; (void)out_size;
}

// round 16
// speedup vs baseline: 1.4293x; 1.4293x over previous
#include <cuda_runtime.h>
#include <cuda_fp16.h>
#include <math.h>
#include <stdint.h>

#define BATCH 8192
#define PDIM  512
#define DM    256
#define DI    512
#define DTR   16
#define DS    16
#define ADIM  64
#define XDW   48

// ---- static scratch ----
__device__ __half g_Ph[BATCH * PDIM];
__device__ __half g_Wh[417792];          // fp16 weights: W_in | in_proj | x_proj
__device__ __half g_WCh[128 * DI];       // combined head weights (fp16)
__device__ __half g_Xh[BATCH * DM];
__device__ __half g_U2h[BATCH * DI];
__device__ __half g_Gh[BATCH * DI];
__device__ float  g_XD[4 * BATCH * XDW]; // x_proj split-K partials (fp32)
__device__ __half g_Yh[BATCH * DI];
__device__ float  g_HP[2 * BATCH * 128]; // heads split-K partials (fp32)

#define OFF_WIN   0
#define OFF_INPJ  131072
#define OFF_XPJ   393216
#define NW_TOTAL  417792
#define NP_TOTAL  (BATCH * PDIM)

__device__ __forceinline__ void mma_f16(float* c, const uint32_t* a,
                                        uint32_t b0, uint32_t b1) {
    asm volatile(
        "mma.sync.aligned.m16n8k16.row.col.f32.f16.f16.f32 "
        "{%0,%1,%2,%3},{%4,%5,%6,%7},{%8,%9},{%0,%1,%2,%3};"
        : "+f"(c[0]), "+f"(c[1]), "+f"(c[2]), "+f"(c[3])
        : "r"(a[0]), "r"(a[1]), "r"(a[2]), "r"(a[3]), "r"(b0), "r"(b1));
}

__device__ __forceinline__ void cp16(uint32_t dst, const void* src, bool ok) {
    int sz = ok ? 16 : 0;
    asm volatile("cp.async.ca.shared.global [%0], [%1], 16, %2;"
                 :: "r"(dst), "l"(src), "r"(sz) : "memory");
}
#define CP_COMMIT() asm volatile("cp.async.commit_group;" ::: "memory")
#define CP_WAIT1()  asm volatile("cp.async.wait_group 1;" ::: "memory")

__device__ __forceinline__ float fast_sigmoid(float x) {
    return __fdividef(1.f, 1.f + __expf(-x));
}
__device__ __forceinline__ float fast_softplus(float x) {
    return (x > 15.f) ? x : __logf(1.f + __expf(x));
}
__device__ __forceinline__ float fast_tanh(float x) {
    float e = __expf(-2.f * fabsf(x));
    float t = __fdividef(1.f - e, 1.f + e);
    return copysignf(t, x);
}

// Convert perception + GEMM weights to fp16.
__global__ void __launch_bounds__(256)
preround(const float* __restrict__ P,
         const float* __restrict__ w_in,  const float* __restrict__ in_proj,
         const float* __restrict__ x_proj,
         __half* __restrict__ gP, __half* __restrict__ gW) {
    int idx = blockIdx.x * 256 + threadIdx.x;
    if (idx < NP_TOTAL) { gP[idx] = __float2half_rn(P[idx]); return; }
    int j = idx - NP_TOTAL;
    if (j >= NW_TOTAL) return;
    float v;
    if      (j < OFF_INPJ) v = w_in[j - OFF_WIN];
    else if (j < OFF_XPJ)  v = in_proj[j - OFF_INPJ];
    else                   v = x_proj[j - OFF_XPJ];
    gW[j] = __float2half_rn(v);
}

// WC[j,d] = sum_m [mu_w;ls_w][j,m] * out_proj[m,d]  (fp32 math, fp16 store)
__global__ void __launch_bounds__(256)
combine_heads(const float* __restrict__ mu_w, const float* __restrict__ ls_w,
              const float* __restrict__ out_proj, __half* __restrict__ WC) {
    __shared__ float sM[64][65];
    __shared__ float sO[64][65];
    const int tid = threadIdx.x;
    const int bj = blockIdx.x * 64, bd = blockIdx.y * 64;
    const int ty = tid >> 4, tx = tid & 15;

    float acc[4][4];
#pragma unroll
    for (int i = 0; i < 4; i++)
#pragma unroll
        for (int j = 0; j < 4; j++) acc[i][j] = 0.f;

    for (int k0 = 0; k0 < DM; k0 += 64) {
        for (int i = tid; i < 64 * 16; i += 256) {
            int r = i >> 4, q = (i & 15) * 4;
            int jr = bj + r;
            const float* src = (jr < ADIM)
                ? (mu_w + (size_t)jr * DM + k0 + q)
                : (ls_w + (size_t)(jr - ADIM) * DM + k0 + q);
            float4 v = *(const float4*)src;
            sM[r][q] = v.x; sM[r][q + 1] = v.y; sM[r][q + 2] = v.z; sM[r][q + 3] = v.w;
        }
        for (int i = tid; i < 64 * 16; i += 256) {
            int r = i >> 4, q = (i & 15) * 4;
            float4 v = *(const float4*)(out_proj + (size_t)(k0 + r) * DI + bd + q);
            sO[r][q] = v.x; sO[r][q + 1] = v.y; sO[r][q + 2] = v.z; sO[r][q + 3] = v.w;
        }
        __syncthreads();
#pragma unroll 8
        for (int k = 0; k < 64; k++) {
            float a[4], b[4];
#pragma unroll
            for (int i = 0; i < 4; i++) { a[i] = sM[ty * 4 + i][k]; b[i] = sO[k][tx * 4 + i]; }
#pragma unroll
            for (int i = 0; i < 4; i++)
#pragma unroll
                for (int j = 0; j < 4; j++) acc[i][j] += a[i] * b[j];
        }
        __syncthreads();
    }
#pragma unroll
    for (int i = 0; i < 4; i++)
#pragma unroll
        for (int j = 0; j < 4; j++)
            WC[(size_t)(bj + ty * 4 + i) * DI + bd + tx * 4 + j] =
                __float2half_rn(acc[i][j]);
}

// ---------- fp16 GEMM: BM=128 BN=64 BK=32, 256 thr, warp 32x32 ----------
// m16n8k16 f16 MMA, fp32 accum. 3-stage cp.async. PAD=40 halves (banks 20g+t).
// EPI: 0 split-K fp32 partial (guard col<Nfull), 1 X=half(v+bias),
//      2 in_proj fused (U2 half | G half)
#define PADH 40
template <int EPI>
__global__ void __launch_bounds__(256)
gemm_h(const __half* __restrict__ A, int lda,
       const __half* __restrict__ W, int ldw, const float* __restrict__ bias,
       void* __restrict__ Cv, int ldc, int Nfull, int K, int pstride,
       const float* __restrict__ aux0, const float* __restrict__ aux1,
       __half* __restrict__ aux2) {
    const int BM = 128, BN = 64, BK = 32;
    __shared__ __half As[3][BM][PADH];
    __shared__ __half Ws[3][BN][PADH];

    const int tid  = threadIdx.x;
    const int lane = tid & 31, wid = tid >> 5;
    const int wm = (wid & 3) * 32, wn = (wid >> 2) * 32;
    const int g = lane >> 2, t = lane & 3;
    const int bm = blockIdx.x * BM;
    const int bn = blockIdx.y * BN;

    const int kz = blockIdx.z * K;
    const __half* Ap = A + kz;
    const __half* Wp = W + kz;

    const int ar0 = tid >> 2;            // 0..63
    const int ak  = (tid & 3) * 8;       // half offset: 0,8,16,24
    const int nTiles = K / BK;

    const bool wok = (bn + ar0) < Nfull;
    const int wrow = wok ? (bn + ar0) : 0;

    uint32_t sA0 = (uint32_t)__cvta_generic_to_shared(&As[0][ar0][ak]);
    uint32_t sA1 = (uint32_t)__cvta_generic_to_shared(&As[0][ar0 + 64][ak]);
    uint32_t sW0 = (uint32_t)__cvta_generic_to_shared(&Ws[0][ar0][ak]);
    const uint32_t bufA = BM * PADH * 2;
    const uint32_t bufW = BN * PADH * 2;

    auto issue = [&](int kt, int b) {
        int k0 = kt * BK + ak;
        cp16(sA0 + b * bufA, Ap + (size_t)(bm + ar0) * lda + k0, true);
        cp16(sA1 + b * bufA, Ap + (size_t)(bm + ar0 + 64) * lda + k0, true);
        cp16(sW0 + b * bufW, Wp + (size_t)wrow * ldw + k0, wok);
    };

    float acc[2][4][4];
#pragma unroll
    for (int i = 0; i < 2; i++)
#pragma unroll
        for (int j = 0; j < 4; j++)
#pragma unroll
            for (int l = 0; l < 4; l++) acc[i][j][l] = 0.f;

    issue(0, 0); CP_COMMIT();
    issue(1, 1); CP_COMMIT();

    int cur = 0;
    for (int kt = 0; kt < nTiles; kt++) {
        CP_WAIT1();
        __syncthreads();
        if (kt + 2 < nTiles) issue(kt + 2, (kt + 2) % 3);
        CP_COMMIT();

#pragma unroll
        for (int ks = 0; ks < 2; ks++) {
            const int kb = ks * 16;      // K=16 per MMA
            uint32_t a[2][4];
#pragma unroll
            for (int mt = 0; mt < 2; mt++) {
                int row = wm + mt * 16 + g;
                a[mt][0] = *(const uint32_t*)&As[cur][row][kb + 2 * t];
                a[mt][1] = *(const uint32_t*)&As[cur][row + 8][kb + 2 * t];
                a[mt][2] = *(const uint32_t*)&As[cur][row][kb + 2 * t + 8];
                a[mt][3] = *(const uint32_t*)&As[cur][row + 8][kb + 2 * t + 8];
            }
#pragma unroll
            for (int nt = 0; nt < 4; nt++) {
                int nc = wn + nt * 8 + g;
                uint32_t b0 = *(const uint32_t*)&Ws[cur][nc][kb + 2 * t];
                uint32_t b1 = *(const uint32_t*)&Ws[cur][nc][kb + 2 * t + 8];
                mma_f16(acc[0][nt], a[0], b0, b1);
                mma_f16(acc[1][nt], a[1], b0, b1);
            }
        }
        cur = (cur + 1) % 3;
    }

#pragma unroll
    for (int mt = 0; mt < 2; mt++) {
#pragma unroll
        for (int nt = 0; nt < 4; nt++) {
#pragma unroll
            for (int ci = 0; ci < 4; ci++) {
                int row = bm + wm + mt * 16 + g + ((ci >= 2) ? 8 : 0);
                int col = bn + wn + nt * 8 + t * 2 + (ci & 1);
                float v = acc[mt][nt][ci];
                if (EPI == 0) {
                    if (col < Nfull)
                        ((float*)Cv)[(size_t)blockIdx.z * pstride +
                                     (size_t)row * ldc + col] = v;
                } else if (EPI == 1) {
                    ((__half*)Cv)[(size_t)row * ldc + col] =
                        __float2half_rn(v + bias[col]);
                } else { // EPI == 2: in_proj fused
                    if (col < DI) {
                        float u = v * aux0[col * 4 + 3] + aux1[col];
                        ((__half*)Cv)[(size_t)row * DI + col] =
                            __float2half_rn(u * fast_sigmoid(u));       // U2
                    } else {
                        aux2[(size_t)row * DI + (col - DI)] =
                            __float2half_rn(v * fast_sigmoid(v));       // G
                    }
                }
            }
        }
    }
}

__global__ void __launch_bounds__(256)
heads_epi(const float* __restrict__ HP, const float* __restrict__ mu_b,
          const float* __restrict__ ls_b, float* __restrict__ out_mu,
          float* __restrict__ out_ls) {
    int idx = (blockIdx.x * 256 + threadIdx.x) * 4;
    int row = idx >> 7, col = idx & 127;
    float4 p0 = *(const float4*)&HP[idx];
    float4 p1 = *(const float4*)&HP[(size_t)BATCH * 128 + idx];
    if (col < ADIM) {
        const float4 b = *(const float4*)&mu_b[col];
        float4 o;
        o.x = fast_tanh(p0.x + p1.x + b.x);
        o.y = fast_tanh(p0.y + p1.y + b.y);
        o.z = fast_tanh(p0.z + p1.z + b.z);
        o.w = fast_tanh(p0.w + p1.w + b.w);
        *(float4*)&out_mu[(size_t)row * ADIM + col] = o;
    } else {
        const float4 b = *(const float4*)&ls_b[col - ADIM];
        float4 o;
        o.x = fminf(fmaxf(p0.x + p1.x + b.x, -5.f), 2.f);
        o.y = fminf(fmaxf(p0.y + p1.y + b.y, -5.f), 2.f);
        o.z = fminf(fmaxf(p0.z + p1.z + b.z, -5.f), 2.f);
        o.w = fminf(fmaxf(p0.w + p1.w + b.w, -5.f), 2.f);
        *(float4*)&out_ls[(size_t)row * ADIM + (col - ADIM)] = o;
    }
}

// Fused: XD = sum of 4 partials; delta = softplus(...); bc = B.C; gate.
// U2/G read as half, Y written as half.
#define RB2 8
__global__ void __launch_bounds__(512)
delta_ygate(const float* __restrict__ XD, const float* __restrict__ dtw,
            const float* __restrict__ dtb, const __half* __restrict__ U2,
            const __half* __restrict__ G, const float* __restrict__ Dskip,
            __half* __restrict__ Y) {
    __shared__ float sXD[RB2][XDW];
    __shared__ float sbc[RB2];
    const int tid = threadIdx.x;
    const int r0 = blockIdx.x * RB2;

    if (tid < RB2 * 12) {
        int r = tid / 12, c4 = (tid % 12) * 4;
        size_t off = (size_t)(r0 + r) * XDW + c4;
        float4 s = *(const float4*)&XD[off];
#pragma unroll
        for (int p = 1; p < 4; p++) {
            float4 xp = *(const float4*)&XD[(size_t)p * BATCH * XDW + off];
            s.x += xp.x; s.y += xp.y; s.z += xp.z; s.w += xp.w;
        }
        *(float4*)&sXD[r][c4] = s;
    }
    __syncthreads();
    if (tid < RB2) {
        float s = 0.f;
#pragma unroll
        for (int k = 0; k < DS; k++) s += sXD[tid][DTR + k] * sXD[tid][DTR + DS + k];
        sbc[tid] = s;
    }

    float w[DTR];
#pragma unroll
    for (int i = 0; i < 4; i++)
        *(float4*)&w[i * 4] = *(const float4*)(dtw + (size_t)tid * DTR + i * 4);
    const float bv = dtb[tid];
    const float dv = Dskip[tid];
    __syncthreads();

    size_t base = (size_t)r0 * DI;
    float u = __half2float(U2[base + tid]);
    float gg = __half2float(G[base + tid]);
#pragma unroll
    for (int r = 0; r < RB2; r++) {
        float un, gn;
        if (r + 1 < RB2) {
            un = __half2float(U2[base + DI + tid]);
            gn = __half2float(G[base + DI + tid]);
        }
        float acc = bv;
#pragma unroll
        for (int k = 0; k < DTR; k++) acc += w[k] * sXD[r][k];
        float de = fast_softplus(acc);
        Y[base + tid] = __float2half_rn(u * (de * sbc[r] + dv) * gg);
        base += DI;
        u = un; gg = gn;
    }
}

extern "C" void kernel_launch(void* const* d_in, const int* in_sizes, int n_in,
                              void* d_out, int out_size) {
    const float* perception = (const float*)d_in[0];
    const float* W_in       = (const float*)d_in[1];
    const float* b_in       = (const float*)d_in[2];
    const float* mu_w       = (const float*)d_in[3];
    const float* mu_b       = (const float*)d_in[4];
    const float* ls_w       = (const float*)d_in[5];
    const float* ls_b       = (const float*)d_in[6];
    const float* in_proj_w  = (const float*)d_in[7];
    const float* conv_w     = (const float*)d_in[8];
    const float* conv_b     = (const float*)d_in[9];
    const float* x_proj_w   = (const float*)d_in[10];
    const float* dt_proj_w  = (const float*)d_in[11];
    const float* dt_proj_b  = (const float*)d_in[12];
    const float* Dskip      = (const float*)d_in[14];
    const float* out_proj_w = (const float*)d_in[15];

    float* out = (float*)d_out;

    __half *P, *Wts, *WC, *X, *U2, *G, *Y;
    float *XD, *HP;
    cudaGetSymbolAddress((void**)&P,   g_Ph);
    cudaGetSymbolAddress((void**)&Wts, g_Wh);
    cudaGetSymbolAddress((void**)&WC,  g_WCh);
    cudaGetSymbolAddress((void**)&X,   g_Xh);
    cudaGetSymbolAddress((void**)&U2,  g_U2h);
    cudaGetSymbolAddress((void**)&G,   g_Gh);
    cudaGetSymbolAddress((void**)&XD,  g_XD);
    cudaGetSymbolAddress((void**)&Y,   g_Yh);
    cudaGetSymbolAddress((void**)&HP,  g_HP);

    const int MB = BATCH / 128;   // 64

    // 0) convert inputs to fp16 + fold heads through out_proj
    preround<<<(NP_TOTAL + NW_TOTAL + 255) / 256, 256>>>(
        perception, W_in, in_proj_w, x_proj_w, P, Wts);
    combine_heads<<<dim3(2, 8), 256>>>(mu_w, ls_w, out_proj_w, WC);

    // 1) X = half(perc @ W_in^T + b_in)      [8192,256] K=512
    gemm_h<1><<<dim3(MB, DM / 64), 256>>>(P, PDIM, Wts + OFF_WIN, PDIM, b_in,
                                          X, DM, DM, PDIM, 0,
                                          nullptr, nullptr, nullptr);
    // 2) in_proj + silu-conv + silu(z)       [8192,1024] K=256 -> U2, G
    gemm_h<2><<<dim3(MB, (2 * DI) / 64), 256>>>(X, DM, Wts + OFF_INPJ, DM,
                                                nullptr, U2, DI, 2 * DI, DM, 0,
                                                conv_w, conv_b, G);
    // 3) XD partials = U2 @ x_proj^T (split-K x4) [8192,48]
    gemm_h<0><<<dim3(MB, 1, 4), 256>>>(U2, DI, Wts + OFF_XPJ, DI, nullptr,
                                       XD, XDW, XDW, 128, BATCH * XDW,
                                       nullptr, nullptr, nullptr);
    // 4) delta + bc + gate -> Y (half)       [8192,512]
    delta_ygate<<<BATCH / RB2, 512>>>(XD, dt_proj_w, dt_proj_b, U2, G, Dskip, Y);
    // 5) head partials = Y @ WC^T (split-K x2) [8192,128]
    gemm_h<0><<<dim3(MB, 2, 2), 256>>>(Y, DI, WC, DI, nullptr,
                                       HP, 128, 128, 256, BATCH * 128,
                                       nullptr, nullptr, nullptr);
    // 6) heads epilogue
    heads_epi<<<(BATCH * 128) / (256 * 4), 256>>>(HP, mu_b, ls_b,
                                                  out, out + (size_t)BATCH * ADIM);
    (void)in_sizes; (void)n_in; (void)out_size;
}

// round 17
// speedup vs baseline: 1.5310x; 1.0712x over previous
#include <cuda_runtime.h>
#include <cuda_fp16.h>
#include <math.h>
#include <stdint.h>

#define BATCH 8192
#define PDIM  512
#define DM    256
#define DI    512
#define DTR   16
#define DS    16
#define ADIM  64
#define XDW   48

// ---- static scratch ----
__device__ __half g_Ph[BATCH * PDIM];
__device__ __half g_Wh[417792];          // fp16 weights: W_in | in_proj | x_proj
__device__ __half g_WCh[128 * DI];       // combined head weights (fp16)
__device__ __half g_Xh[BATCH * DM];
__device__ __half g_U2h[BATCH * DI];
__device__ __half g_Gh[BATCH * DI];
__device__ float  g_XD[4 * BATCH * XDW]; // x_proj split-K partials (fp32)
__device__ __half g_Yh[BATCH * DI];
__device__ float  g_HP[2 * BATCH * 128]; // heads split-K partials (fp32)

#define OFF_WIN   0
#define OFF_INPJ  131072
#define OFF_XPJ   393216
#define NW_TOTAL  417792
#define NP_TOTAL  (BATCH * PDIM)

__device__ __forceinline__ void mma_f16(float* c, const uint32_t* a,
                                        uint32_t b0, uint32_t b1) {
    asm volatile(
        "mma.sync.aligned.m16n8k16.row.col.f32.f16.f16.f32 "
        "{%0,%1,%2,%3},{%4,%5,%6,%7},{%8,%9},{%0,%1,%2,%3};"
        : "+f"(c[0]), "+f"(c[1]), "+f"(c[2]), "+f"(c[3])
        : "r"(a[0]), "r"(a[1]), "r"(a[2]), "r"(a[3]), "r"(b0), "r"(b1));
}

#define LDSM_X4(r0, r1, r2, r3, addr)                                       \
    asm volatile("ldmatrix.sync.aligned.m8n8.x4.shared.b16 "                \
                 "{%0,%1,%2,%3}, [%4];"                                     \
                 : "=r"(r0), "=r"(r1), "=r"(r2), "=r"(r3) : "r"(addr))

__device__ __forceinline__ void cp16(uint32_t dst, const void* src, bool ok) {
    int sz = ok ? 16 : 0;
    asm volatile("cp.async.ca.shared.global [%0], [%1], 16, %2;"
                 :: "r"(dst), "l"(src), "r"(sz) : "memory");
}
#define CP_COMMIT() asm volatile("cp.async.commit_group;" ::: "memory")
#define CP_WAIT1()  asm volatile("cp.async.wait_group 1;" ::: "memory")

__device__ __forceinline__ float fast_sigmoid(float x) {
    return __fdividef(1.f, 1.f + __expf(-x));
}
__device__ __forceinline__ float fast_softplus(float x) {
    return (x > 15.f) ? x : __logf(1.f + __expf(x));
}
__device__ __forceinline__ float fast_tanh(float x) {
    float e = __expf(-2.f * fabsf(x));
    float t = __fdividef(1.f - e, 1.f + e);
    return copysignf(t, x);
}

// Convert perception + GEMM weights to fp16.
__global__ void __launch_bounds__(256)
preround(const float* __restrict__ P,
         const float* __restrict__ w_in,  const float* __restrict__ in_proj,
         const float* __restrict__ x_proj,
         __half* __restrict__ gP, __half* __restrict__ gW) {
    int idx = blockIdx.x * 256 + threadIdx.x;
    if (idx < NP_TOTAL) { gP[idx] = __float2half_rn(P[idx]); return; }
    int j = idx - NP_TOTAL;
    if (j >= NW_TOTAL) return;
    float v;
    if      (j < OFF_INPJ) v = w_in[j - OFF_WIN];
    else if (j < OFF_XPJ)  v = in_proj[j - OFF_INPJ];
    else                   v = x_proj[j - OFF_XPJ];
    gW[j] = __float2half_rn(v);
}

// WC[j,d] = sum_m [mu_w;ls_w][j,m] * out_proj[m,d]  (fp32 math, fp16 store)
__global__ void __launch_bounds__(256)
combine_heads(const float* __restrict__ mu_w, const float* __restrict__ ls_w,
              const float* __restrict__ out_proj, __half* __restrict__ WC) {
    __shared__ float sM[64][65];
    __shared__ float sO[64][65];
    const int tid = threadIdx.x;
    const int bj = blockIdx.x * 64, bd = blockIdx.y * 64;
    const int ty = tid >> 4, tx = tid & 15;

    float acc[4][4];
#pragma unroll
    for (int i = 0; i < 4; i++)
#pragma unroll
        for (int j = 0; j < 4; j++) acc[i][j] = 0.f;

    for (int k0 = 0; k0 < DM; k0 += 64) {
        for (int i = tid; i < 64 * 16; i += 256) {
            int r = i >> 4, q = (i & 15) * 4;
            int jr = bj + r;
            const float* src = (jr < ADIM)
                ? (mu_w + (size_t)jr * DM + k0 + q)
                : (ls_w + (size_t)(jr - ADIM) * DM + k0 + q);
            float4 v = *(const float4*)src;
            sM[r][q] = v.x; sM[r][q + 1] = v.y; sM[r][q + 2] = v.z; sM[r][q + 3] = v.w;
        }
        for (int i = tid; i < 64 * 16; i += 256) {
            int r = i >> 4, q = (i & 15) * 4;
            float4 v = *(const float4*)(out_proj + (size_t)(k0 + r) * DI + bd + q);
            sO[r][q] = v.x; sO[r][q + 1] = v.y; sO[r][q + 2] = v.z; sO[r][q + 3] = v.w;
        }
        __syncthreads();
#pragma unroll 8
        for (int k = 0; k < 64; k++) {
            float a[4], b[4];
#pragma unroll
            for (int i = 0; i < 4; i++) { a[i] = sM[ty * 4 + i][k]; b[i] = sO[k][tx * 4 + i]; }
#pragma unroll
            for (int i = 0; i < 4; i++)
#pragma unroll
                for (int j = 0; j < 4; j++) acc[i][j] += a[i] * b[j];
        }
        __syncthreads();
    }
#pragma unroll
    for (int i = 0; i < 4; i++)
#pragma unroll
        for (int j = 0; j < 4; j++)
            WC[(size_t)(bj + ty * 4 + i) * DI + bd + tx * 4 + j] =
                __float2half_rn(acc[i][j]);
}

// ---------- fp16 GEMM: BM=128 BN=64 BK=32, 256 thr, warp 32x32 ----------
// m16n8k16 f16 MMA via ldmatrix.x4 fragments. 3-stage cp.async. PAD=40 halves.
// EPI: 0 split-K fp32 partial (guard col<Nfull), 1 X=half(v+bias),
//      2 in_proj fused (U2 half | G half)
#define PADH 40
template <int EPI>
__global__ void __launch_bounds__(256)
gemm_h(const __half* __restrict__ A, int lda,
       const __half* __restrict__ W, int ldw, const float* __restrict__ bias,
       void* __restrict__ Cv, int ldc, int Nfull, int K, int pstride,
       const float* __restrict__ aux0, const float* __restrict__ aux1,
       __half* __restrict__ aux2) {
    const int BM = 128, BN = 64, BK = 32;
    __shared__ __half As[3][BM][PADH];
    __shared__ __half Ws[3][BN][PADH];

    const int tid  = threadIdx.x;
    const int lane = tid & 31, wid = tid >> 5;
    const int wm = (wid & 3) * 32, wn = (wid >> 2) * 32;
    const int g = lane >> 2, t = lane & 3;
    const int bm = blockIdx.x * BM;
    const int bn = blockIdx.y * BN;

    const int kz = blockIdx.z * K;
    const __half* Ap = A + kz;
    const __half* Wp = W + kz;

    const int ar0 = tid >> 2;            // 0..63
    const int ak  = (tid & 3) * 8;       // half offset: 0,8,16,24
    const int nTiles = K / BK;

    const bool wok = (bn + ar0) < Nfull;
    const int wrow = wok ? (bn + ar0) : 0;

    uint32_t sA0 = (uint32_t)__cvta_generic_to_shared(&As[0][ar0][ak]);
    uint32_t sA1 = (uint32_t)__cvta_generic_to_shared(&As[0][ar0 + 64][ak]);
    uint32_t sW0 = (uint32_t)__cvta_generic_to_shared(&Ws[0][ar0][ak]);
    const uint32_t bufA = BM * PADH * 2;
    const uint32_t bufW = BN * PADH * 2;

    // ldmatrix lane addressing: lm = matrix index group, lr = row within 8x8
    const int lm = lane >> 3, lr = lane & 7;
    // A x4: matrices (rows0-7,k0-7)(rows8-15,k0-7)(rows0-7,k8-15)(rows8-15,k8-15)
    uint32_t aAddr[2];
#pragma unroll
    for (int mt = 0; mt < 2; mt++)
        aAddr[mt] = (uint32_t)__cvta_generic_to_shared(
            &As[0][wm + mt * 16 + (lm & 1) * 8 + lr][(lm >> 1) * 8]);
    // B x4 (two n-tiles): matrices (nt,k0-7)(nt,k8-15)(nt+1,k0-7)(nt+1,k8-15)
    uint32_t bAddr[2];
#pragma unroll
    for (int p = 0; p < 2; p++)
        bAddr[p] = (uint32_t)__cvta_generic_to_shared(
            &Ws[0][wn + (p * 2 + (lm >> 1)) * 8 + lr][(lm & 1) * 8]);

    auto issue = [&](int kt, int b) {
        int k0 = kt * BK + ak;
        cp16(sA0 + b * bufA, Ap + (size_t)(bm + ar0) * lda + k0, true);
        cp16(sA1 + b * bufA, Ap + (size_t)(bm + ar0 + 64) * lda + k0, true);
        cp16(sW0 + b * bufW, Wp + (size_t)wrow * ldw + k0, wok);
    };

    float acc[2][4][4];
#pragma unroll
    for (int i = 0; i < 2; i++)
#pragma unroll
        for (int j = 0; j < 4; j++)
#pragma unroll
            for (int l = 0; l < 4; l++) acc[i][j][l] = 0.f;

    issue(0, 0); CP_COMMIT();
    issue(1, 1); CP_COMMIT();

    int cur = 0;
    for (int kt = 0; kt < nTiles; kt++) {
        CP_WAIT1();
        __syncthreads();
        if (kt + 2 < nTiles) issue(kt + 2, (kt + 2) % 3);
        CP_COMMIT();

        const uint32_t offA = cur * bufA;
        const uint32_t offW = cur * bufW;
#pragma unroll
        for (int ks = 0; ks < 2; ks++) {
            const uint32_t kbB = ks * 32;        // 16 halves = 32 bytes
            uint32_t a[2][4];
            LDSM_X4(a[0][0], a[0][1], a[0][2], a[0][3], aAddr[0] + offA + kbB);
            LDSM_X4(a[1][0], a[1][1], a[1][2], a[1][3], aAddr[1] + offA + kbB);
            uint32_t b[4][2];
            LDSM_X4(b[0][0], b[0][1], b[1][0], b[1][1], bAddr[0] + offW + kbB);
            LDSM_X4(b[2][0], b[2][1], b[3][0], b[3][1], bAddr[1] + offW + kbB);
#pragma unroll
            for (int nt = 0; nt < 4; nt++) {
                mma_f16(acc[0][nt], a[0], b[nt][0], b[nt][1]);
                mma_f16(acc[1][nt], a[1], b[nt][0], b[nt][1]);
            }
        }
        cur = (cur + 1) % 3;
    }

#pragma unroll
    for (int mt = 0; mt < 2; mt++) {
#pragma unroll
        for (int nt = 0; nt < 4; nt++) {
#pragma unroll
            for (int ci = 0; ci < 4; ci++) {
                int row = bm + wm + mt * 16 + g + ((ci >= 2) ? 8 : 0);
                int col = bn + wn + nt * 8 + t * 2 + (ci & 1);
                float v = acc[mt][nt][ci];
                if (EPI == 0) {
                    if (col < Nfull)
                        ((float*)Cv)[(size_t)blockIdx.z * pstride +
                                     (size_t)row * ldc + col] = v;
                } else if (EPI == 1) {
                    ((__half*)Cv)[(size_t)row * ldc + col] =
                        __float2half_rn(v + bias[col]);
                } else { // EPI == 2: in_proj fused
                    if (col < DI) {
                        float u = v * aux0[col * 4 + 3] + aux1[col];
                        ((__half*)Cv)[(size_t)row * DI + col] =
                            __float2half_rn(u * fast_sigmoid(u));       // U2
                    } else {
                        aux2[(size_t)row * DI + (col - DI)] =
                            __float2half_rn(v * fast_sigmoid(v));       // G
                    }
                }
            }
        }
    }
}

__global__ void __launch_bounds__(256)
heads_epi(const float* __restrict__ HP, const float* __restrict__ mu_b,
          const float* __restrict__ ls_b, float* __restrict__ out_mu,
          float* __restrict__ out_ls) {
    int idx = (blockIdx.x * 256 + threadIdx.x) * 4;
    int row = idx >> 7, col = idx & 127;
    float4 p0 = *(const float4*)&HP[idx];
    float4 p1 = *(const float4*)&HP[(size_t)BATCH * 128 + idx];
    if (col < ADIM) {
        const float4 b = *(const float4*)&mu_b[col];
        float4 o;
        o.x = fast_tanh(p0.x + p1.x + b.x);
        o.y = fast_tanh(p0.y + p1.y + b.y);
        o.z = fast_tanh(p0.z + p1.z + b.z);
        o.w = fast_tanh(p0.w + p1.w + b.w);
        *(float4*)&out_mu[(size_t)row * ADIM + col] = o;
    } else {
        const float4 b = *(const float4*)&ls_b[col - ADIM];
        float4 o;
        o.x = fminf(fmaxf(p0.x + p1.x + b.x, -5.f), 2.f);
        o.y = fminf(fmaxf(p0.y + p1.y + b.y, -5.f), 2.f);
        o.z = fminf(fmaxf(p0.z + p1.z + b.z, -5.f), 2.f);
        o.w = fminf(fmaxf(p0.w + p1.w + b.w, -5.f), 2.f);
        *(float4*)&out_ls[(size_t)row * ADIM + (col - ADIM)] = o;
    }
}

// Fused: XD = sum of 4 partials; delta = softplus(...); bc = B.C; gate.
#define RB2 8
__global__ void __launch_bounds__(512)
delta_ygate(const float* __restrict__ XD, const float* __restrict__ dtw,
            const float* __restrict__ dtb, const __half* __restrict__ U2,
            const __half* __restrict__ G, const float* __restrict__ Dskip,
            __half* __restrict__ Y) {
    __shared__ float sXD[RB2][XDW];
    __shared__ float sbc[RB2];
    const int tid = threadIdx.x;
    const int r0 = blockIdx.x * RB2;

    if (tid < RB2 * 12) {
        int r = tid / 12, c4 = (tid % 12) * 4;
        size_t off = (size_t)(r0 + r) * XDW + c4;
        float4 s = *(const float4*)&XD[off];
#pragma unroll
        for (int p = 1; p < 4; p++) {
            float4 xp = *(const float4*)&XD[(size_t)p * BATCH * XDW + off];
            s.x += xp.x; s.y += xp.y; s.z += xp.z; s.w += xp.w;
        }
        *(float4*)&sXD[r][c4] = s;
    }
    __syncthreads();
    if (tid < RB2) {
        float s = 0.f;
#pragma unroll
        for (int k = 0; k < DS; k++) s += sXD[tid][DTR + k] * sXD[tid][DTR + DS + k];
        sbc[tid] = s;
    }

    float w[DTR];
#pragma unroll
    for (int i = 0; i < 4; i++)
        *(float4*)&w[i * 4] = *(const float4*)(dtw + (size_t)tid * DTR + i * 4);
    const float bv = dtb[tid];
    const float dv = Dskip[tid];
    __syncthreads();

    size_t base = (size_t)r0 * DI;
    float u = __half2float(U2[base + tid]);
    float gg = __half2float(G[base + tid]);
#pragma unroll
    for (int r = 0; r < RB2; r++) {
        float un, gn;
        if (r + 1 < RB2) {
            un = __half2float(U2[base + DI + tid]);
            gn = __half2float(G[base + DI + tid]);
        }
        float acc = bv;
#pragma unroll
        for (int k = 0; k < DTR; k++) acc += w[k] * sXD[r][k];
        float de = fast_softplus(acc);
        Y[base + tid] = __float2half_rn(u * (de * sbc[r] + dv) * gg);
        base += DI;
        u = un; gg = gn;
    }
}

extern "C" void kernel_launch(void* const* d_in, const int* in_sizes, int n_in,
                              void* d_out, int out_size) {
    const float* perception = (const float*)d_in[0];
    const float* W_in       = (const float*)d_in[1];
    const float* b_in       = (const float*)d_in[2];
    const float* mu_w       = (const float*)d_in[3];
    const float* mu_b       = (const float*)d_in[4];
    const float* ls_w       = (const float*)d_in[5];
    const float* ls_b       = (const float*)d_in[6];
    const float* in_proj_w  = (const float*)d_in[7];
    const float* conv_w     = (const float*)d_in[8];
    const float* conv_b     = (const float*)d_in[9];
    const float* x_proj_w   = (const float*)d_in[10];
    const float* dt_proj_w  = (const float*)d_in[11];
    const float* dt_proj_b  = (const float*)d_in[12];
    const float* Dskip      = (const float*)d_in[14];
    const float* out_proj_w = (const float*)d_in[15];

    float* out = (float*)d_out;

    __half *P, *Wts, *WC, *X, *U2, *G, *Y;
    float *XD, *HP;
    cudaGetSymbolAddress((void**)&P,   g_Ph);
    cudaGetSymbolAddress((void**)&Wts, g_Wh);
    cudaGetSymbolAddress((void**)&WC,  g_WCh);
    cudaGetSymbolAddress((void**)&X,   g_Xh);
    cudaGetSymbolAddress((void**)&U2,  g_U2h);
    cudaGetSymbolAddress((void**)&G,   g_Gh);
    cudaGetSymbolAddress((void**)&XD,  g_XD);
    cudaGetSymbolAddress((void**)&Y,   g_Yh);
    cudaGetSymbolAddress((void**)&HP,  g_HP);

    const int MB = BATCH / 128;   // 64

    // 0) convert inputs to fp16 + fold heads through out_proj
    preround<<<(NP_TOTAL + NW_TOTAL + 255) / 256, 256>>>(
        perception, W_in, in_proj_w, x_proj_w, P, Wts);
    combine_heads<<<dim3(2, 8), 256>>>(mu_w, ls_w, out_proj_w, WC);

    // 1) X = half(perc @ W_in^T + b_in)      [8192,256] K=512
    gemm_h<1><<<dim3(MB, DM / 64), 256>>>(P, PDIM, Wts + OFF_WIN, PDIM, b_in,
                                          X, DM, DM, PDIM, 0,
                                          nullptr, nullptr, nullptr);
    // 2) in_proj + silu-conv + silu(z)       [8192,1024] K=256 -> U2, G
    gemm_h<2><<<dim3(MB, (2 * DI) / 64), 256>>>(X, DM, Wts + OFF_INPJ, DM,
                                                nullptr, U2, DI, 2 * DI, DM, 0,
                                                conv_w, conv_b, G);
    // 3) XD partials = U2 @ x_proj^T (split-K x4) [8192,48]
    gemm_h<0><<<dim3(MB, 1, 4), 256>>>(U2, DI, Wts + OFF_XPJ, DI, nullptr,
                                       XD, XDW, XDW, 128, BATCH * XDW,
                                       nullptr, nullptr, nullptr);
    // 4) delta + bc + gate -> Y (half)       [8192,512]
    delta_ygate<<<BATCH / RB2, 512>>>(XD, dt_proj_w, dt_proj_b, U2, G, Dskip, Y);
    // 5) head partials = Y @ WC^T (split-K x2) [8192,128]
    gemm_h<0><<<dim3(MB, 2, 2), 256>>>(Y, DI, WC, DI, nullptr,
                                       HP, 128, 128, 256, BATCH * 128,
                                       nullptr, nullptr, nullptr);
    // 6) heads epilogue
    heads_epi<<<(BATCH * 128) / (256 * 4), 256>>>(HP, mu_b, ls_b,
                                                  out, out + (size_t)BATCH * ADIM);
    (void)in_sizes; (void)n_in; (void)out_size;
}